// round 11
// baseline (speedup 1.0000x reference)
#include <cuda_runtime.h>
#include <cstdint>

#define SS 2048
#define DD 64
#define NH 16
#define NB 2
#define NEGV -1000000000.0f

// ---- pass1 smem (floats) ----
#define K1_DB  0                   // K db: 2 x 2048 floats (8KB tiles)
#define K1_MB  4096                // mask db: 2 x 128 words
#define K1_FLOATS 4352             // 17,408 B

// ---- pass2 smem (floats) ----
#define K2_DB 0                    // V db: 2 x 2048 floats
#define K2_FLOATS 4096             // 16,384 B

// packed scratch: 64 tiles of 2048 floats per bh
__device__ float    g_kpk[(size_t)NB*NH*64*2048];
__device__ float    g_vpk[(size_t)NB*NH*64*2048];
__device__ unsigned g_mbits[(size_t)NB*SS*64];
__device__ float    g_li[(size_t)NB*NH*SS];

#define MMA_BF16(d, a0,a1,a2,a3, b0,b1) \
    asm volatile("mma.sync.aligned.m16n8k16.row.col.f32.bf16.bf16.f32 " \
        "{%0,%1,%2,%3}, {%4,%5,%6,%7}, {%8,%9}, {%0,%1,%2,%3};" \
        : "+f"((d)[0]), "+f"((d)[1]), "+f"((d)[2]), "+f"((d)[3]) \
        : "r"(a0), "r"(a1), "r"(a2), "r"(a3), "r"(b0), "r"(b1))

__device__ __forceinline__ uint32_t bf16pair(float x0, float x1) {
    uint32_t r;
    asm("cvt.rn.bf16x2.f32 %0, %1, %2;" : "=r"(r) : "f"(x1), "f"(x0));
    return r;
}
__device__ __forceinline__ void split_pair(float x0, float x1, uint32_t& hi, uint32_t& lo) {
    hi = bf16pair(x0, x1);
    float h0 = __uint_as_float(hi << 16);
    float h1 = __uint_as_float(hi & 0xffff0000u);
    lo = bf16pair(x0 - h0, x1 - h1);
}
__device__ __forceinline__ uint32_t smem_u32(const void* p) {
    uint32_t a;
    asm("{ .reg .u64 t; cvta.to.shared.u64 t, %1; cvt.u32.u64 %0, t; }" : "=r"(a) : "l"(p));
    return a;
}
// K slot (order {h0,h1,l0,l1}): 64 floats/row, kk 0..3
__device__ __forceinline__ int pk_k(int row, int kk, int tg) {
    return row*64 + ((((kk ^ (row & 3)) << 2) | tg) << 2);
}
// V slot (order {h0,h1,l0,l1}): 32 floats/row, kk 0..1
__device__ __forceinline__ int pk_v(int d, int kk, int tg) {
    return d*32 + ((((kk ^ (d & 1)) << 2) | tg) << 2);
}
__device__ __forceinline__ void cp16(uint32_t dst, const void* src) {
    asm volatile("cp.async.cg.shared.global [%0], [%1], 16;" :: "r"(dst), "l"(src));
}
__device__ __forceinline__ void cp4(uint32_t dst, const void* src) {
    asm volatile("cp.async.ca.shared.global [%0], [%1], 4;" :: "r"(dst), "l"(src));
}
__device__ __forceinline__ void cp_commit() { asm volatile("cp.async.commit_group;"); }
__device__ __forceinline__ void cp_wait0()  { asm volatile("cp.async.wait_group 0;" ::: "memory"); }

__device__ __forceinline__ void cp_tile8(uint32_t dst_byte, const float* src, int tid) {
    cp16(dst_byte + tid*16, src + tid*4);
    cp16(dst_byte + (tid+256)*16, src + (tid+256)*4);
}

// ---------------- prologue kernels ----------------
__global__ void pack_k_kernel(const float* __restrict__ kg) {
    const int kt = blockIdx.x, h = blockIdx.y, b = blockIdx.z;
    const int bh = b*NH + h;
    const float* base = kg + ((size_t)bh*SS + kt*32) * DD;
    float* out = g_kpk + ((size_t)bh*64 + kt) * 2048;
    for (int s = threadIdx.x; s < 512; s += 256) {
        int r = s >> 4, kk = (s >> 2) & 3, tg = s & 3;
        int c0 = kk*16 + tg*2;
        const float* kp = base + (size_t)r*DD;
        uint32_t bh0, bl0, bh1, bl1;
        split_pair(kp[c0],   kp[c0+1], bh0, bl0);
        split_pair(kp[c0+8], kp[c0+9], bh1, bl1);
        *reinterpret_cast<uint4*>(out + pk_k(r, kk, tg)) = make_uint4(bh0, bh1, bl0, bl1);
    }
}

__global__ void pack_v_kernel(const float* __restrict__ vg) {
    __shared__ float Vs[32*65];
    const int kt = blockIdx.x, h = blockIdx.y, b = blockIdx.z;
    const int bh = b*NH + h;
    const float* base = vg + ((size_t)bh*SS + kt*32) * DD;
    float* out = g_vpk + ((size_t)bh*64 + kt) * 2048;
    for (int i = threadIdx.x; i < 32*16; i += 256) {
        int k = i >> 4, d4 = (i & 15) << 2;
        float4 v = *reinterpret_cast<const float4*>(base + (size_t)k*DD + d4);
        Vs[k*65 + d4 + 0] = v.x; Vs[k*65 + d4 + 1] = v.y;
        Vs[k*65 + d4 + 2] = v.z; Vs[k*65 + d4 + 3] = v.w;
    }
    __syncthreads();
    for (int s = threadIdx.x; s < 512; s += 256) {
        int d = s >> 3, kk = (s >> 2) & 1, tg = s & 3;
        int c0 = kk*16 + tg*2;
        uint32_t bh0, bl0, bh1, bl1;
        split_pair(Vs[c0*65 + d],     Vs[(c0+1)*65 + d], bh0, bl0);
        split_pair(Vs[(c0+8)*65 + d], Vs[(c0+9)*65 + d], bh1, bl1);
        *reinterpret_cast<uint4*>(out + pk_v(d, kk, tg)) = make_uint4(bh0, bh1, bl0, bl1);
    }
}

__global__ void pack_mask_kernel(const int* __restrict__ maskg) {
    int gt = blockIdx.x*256 + threadIdx.x;
    int widx = gt >> 5;
    int lane = gt & 31;
    int w = widx & 63;
    int row = (widx >> 6) & (SS - 1);
    int b = widx >> 17;
    int c = w*32 + lane;
    unsigned nz = maskg[((size_t)b*SS + row)*SS + c] != 0;
    unsigned bits = __ballot_sync(0xffffffffu, nz);
    if (lane == 0) g_mbits[widx] = bits;
}

// ---------------- pass 1: scores + attn + 1/l ----------------
__global__ __launch_bounds__(256, 3)
void sdpa_pass1_kernel(const float* __restrict__ qg, float* __restrict__ attng)
{
    extern __shared__ float sm[];
    unsigned* maskbuf = reinterpret_cast<unsigned*>(sm + K1_MB);
    const uint32_t db_byte = smem_u32(sm + K1_DB);
    const uint32_t mb_byte = smem_u32(sm + K1_MB);

    const int tid = threadIdx.x;
    const int wid = tid >> 5;
    const int lid = tid & 31;
    const int grp = lid >> 2;
    const int tig = lid & 3;
    const int mrow0 = wid * 16;
    const int g3 = grp & 3;

    const int q0 = blockIdx.x * 128;
    const int h  = blockIdx.y;
    const int b  = blockIdx.z;
    const int bh = b*NH + h;

    const float* qbase = qg + ((size_t)bh*SS + q0) * DD;
    float* attnbase = attng + ((size_t)bh*SS + q0) * SS;
    const float* kpk = g_kpk + (size_t)bh*64*2048;
    const unsigned* mbits = g_mbits + ((size_t)b*SS + q0)*64;

    // prefetch K tile 0 + mask col 0
    cp_tile8(db_byte, kpk, tid);
    if (tid < 128) cp4(mb_byte + tid*4, mbits + (size_t)tid*64);
    cp_commit();

    // ---- Q fragments resident in registers (pre-scaled by 0.125, exact) ----
    const int r0 = mrow0 + grp, r1 = r0 + 8;
    uint32_t qh[4][4], ql[4][4];
    #pragma unroll
    for (int kk = 0; kk < 4; kk++) {
        const int c0 = kk*16 + 2*tig;
        float2 x00 = *reinterpret_cast<const float2*>(qbase + (size_t)r0*DD + c0);
        float2 x10 = *reinterpret_cast<const float2*>(qbase + (size_t)r1*DD + c0);
        float2 x01 = *reinterpret_cast<const float2*>(qbase + (size_t)r0*DD + c0 + 8);
        float2 x11 = *reinterpret_cast<const float2*>(qbase + (size_t)r1*DD + c0 + 8);
        split_pair(x00.x*0.125f, x00.y*0.125f, qh[kk][0], ql[kk][0]);
        split_pair(x10.x*0.125f, x10.y*0.125f, qh[kk][1], ql[kk][1]);
        split_pair(x01.x*0.125f, x01.y*0.125f, qh[kk][2], ql[kk][2]);
        split_pair(x11.x*0.125f, x11.y*0.125f, qh[kk][3], ql[kk][3]);
    }

    float lrun[2] = {0.0f, 0.0f};

    for (int t = 0; t < 64; t++) {
        cp_wait0();
        __syncthreads();
        if (t < 63) {
            cp_tile8(db_byte + ((t+1)&1)*8192, kpk + (size_t)(t+1)*2048, tid);
            if (tid < 128)
                cp4(mb_byte + ((t+1)&1)*512 + tid*4, mbits + (size_t)tid*64 + (t+1));
            cp_commit();
        }

        const float* kbuf = sm + K1_DB + (t&1)*2048;
        const float* bbase = kbuf + grp*64 + tig*4;

        float acc[4][4];
        #pragma unroll
        for (int n = 0; n < 4; n++) {
            acc[n][0] = 0.f; acc[n][1] = 0.f; acc[n][2] = 0.f; acc[n][3] = 0.f;
        }

        #pragma unroll
        for (int kk = 0; kk < 4; kk++) {
            const float* bk = bbase + ((kk ^ g3) << 4);
            #pragma unroll
            for (int n = 0; n < 4; n++) {
                uint4 bv = *reinterpret_cast<const uint4*>(bk + n*512);
                MMA_BF16(acc[n], qh[kk][0], qh[kk][1], qh[kk][2], qh[kk][3], bv.x, bv.y);
                MMA_BF16(acc[n], qh[kk][0], qh[kk][1], qh[kk][2], qh[kk][3], bv.z, bv.w);
                MMA_BF16(acc[n], ql[kk][0], ql[kk][1], ql[kk][2], ql[kk][3], bv.x, bv.y);
            }
        }

        // epilogue: mask + attn STG + running row-sums (no max subtraction)
        const unsigned word0 = maskbuf[(t&1)*128 + r0];
        const unsigned word1 = maskbuf[(t&1)*128 + r1];
        float ls0 = 0.0f, ls1 = 0.0f;
        #pragma unroll
        for (int n = 0; n < 4; n++) {
            const int c = n*8 + 2*tig;
            float s0 = acc[n][0] + (((word0 >> c) & 1u) ? 0.0f : NEGV);
            float s1 = acc[n][1] + (((word0 >> (c+1)) & 1u) ? 0.0f : NEGV);
            float s2 = acc[n][2] + (((word1 >> c) & 1u) ? 0.0f : NEGV);
            float s3 = acc[n][3] + (((word1 >> (c+1)) & 1u) ? 0.0f : NEGV);
            const int kcol = t*32 + c;
            *reinterpret_cast<float2*>(attnbase + (size_t)r0*SS + kcol) = make_float2(s0, s1);
            *reinterpret_cast<float2*>(attnbase + (size_t)r1*SS + kcol) = make_float2(s2, s3);
            ls0 += __expf(s0) + __expf(s1);
            ls1 += __expf(s2) + __expf(s3);
        }
        lrun[0] += ls0;
        lrun[1] += ls1;
    }

    // combine row-sums across the 4 tig lanes
    #pragma unroll
    for (int hh = 0; hh < 2; hh++) {
        float l = lrun[hh];
        l += __shfl_xor_sync(0xffffffffu, l, 1);
        l += __shfl_xor_sync(0xffffffffu, l, 2);
        lrun[hh] = l;
    }
    if (tig == 0) {
        float* lib = g_li + (size_t)bh*SS + q0;
        lib[r0] = 1.0f / lrun[0];
        lib[r1] = 1.0f / lrun[1];
    }
}

// ---------------- pass 2: prob + O ----------------
__global__ __launch_bounds__(256, 3)
void sdpa_pass2_kernel(float* __restrict__ outg, float* __restrict__ probg,
                       const float* __restrict__ attng)
{
    extern __shared__ float sm[];
    const uint32_t db_byte = smem_u32(sm + K2_DB);

    const int tid = threadIdx.x;
    const int wid = tid >> 5;
    const int lid = tid & 31;
    const int grp = lid >> 2;
    const int tig = lid & 3;
    const int mrow0 = wid * 16;
    const int g1 = grp & 1;

    const int q0 = blockIdx.x * 128;
    const int h  = blockIdx.y;
    const int b  = blockIdx.z;
    const int bh = b*NH + h;

    const float* attnbase = attng + ((size_t)bh*SS + q0) * SS;
    float* probbase = probg + ((size_t)bh*SS + q0) * SS;
    float* outbase  = outg  + ((size_t)bh*SS + q0) * DD;
    const float* vpk = g_vpk + (size_t)bh*64*2048;

    const int r0 = mrow0 + grp, r1 = r0 + 8;
    const float li0 = g_li[(size_t)bh*SS + q0 + r0];
    const float li1 = g_li[(size_t)bh*SS + q0 + r1];

    cp_tile8(db_byte, vpk, tid);
    cp_commit();

    float oacc[8][4];
    #pragma unroll
    for (int n = 0; n < 8; n++) {
        oacc[n][0] = 0.f; oacc[n][1] = 0.f; oacc[n][2] = 0.f; oacc[n][3] = 0.f;
    }

    for (int t = 0; t < 64; t++) {
        cp_wait0();
        __syncthreads();
        if (t < 63) {
            cp_tile8(db_byte + ((t+1)&1)*8192, vpk + (size_t)(t+1)*2048, tid);
            cp_commit();
        }

        const float* vbuf = sm + K2_DB + (t&1)*2048;
        #pragma unroll
        for (int kk = 0; kk < 2; kk++) {
            const int c0 = t*32 + kk*16 + 2*tig;
            // read attn directly in fragment layout
            float2 s00 = *reinterpret_cast<const float2*>(attnbase + (size_t)r0*SS + c0);
            float2 s10 = *reinterpret_cast<const float2*>(attnbase + (size_t)r1*SS + c0);
            float2 s01 = *reinterpret_cast<const float2*>(attnbase + (size_t)r0*SS + c0 + 8);
            float2 s11 = *reinterpret_cast<const float2*>(attnbase + (size_t)r1*SS + c0 + 8);
            // prob = exp(s) * (1/l)   (no max shift; masked -> exp = 0 exactly)
            float2 p00 = make_float2(__expf(s00.x)*li0, __expf(s00.y)*li0);
            float2 p10 = make_float2(__expf(s10.x)*li1, __expf(s10.y)*li1);
            float2 p01 = make_float2(__expf(s01.x)*li0, __expf(s01.y)*li0);
            float2 p11 = make_float2(__expf(s11.x)*li1, __expf(s11.y)*li1);
            *reinterpret_cast<float2*>(probbase + (size_t)r0*SS + c0)     = p00;
            *reinterpret_cast<float2*>(probbase + (size_t)r1*SS + c0)     = p10;
            *reinterpret_cast<float2*>(probbase + (size_t)r0*SS + c0 + 8) = p01;
            *reinterpret_cast<float2*>(probbase + (size_t)r1*SS + c0 + 8) = p11;
            // split to bf16 fragments in-register
            uint32_t ah0, al0, ah1, al1, ah2, al2, ah3, al3;
            split_pair(p00.x, p00.y, ah0, al0);
            split_pair(p10.x, p10.y, ah1, al1);
            split_pair(p01.x, p01.y, ah2, al2);
            split_pair(p11.x, p11.y, ah3, al3);
            const float* vb = vbuf + grp*32 + tig*4 + ((kk ^ g1) << 4);
            #pragma unroll
            for (int n = 0; n < 8; n++) {
                uint4 bv = *reinterpret_cast<const uint4*>(vb + n*256);
                MMA_BF16(oacc[n], ah0, ah1, ah2, ah3, bv.x, bv.y);   // hi*hi
                MMA_BF16(oacc[n], ah0, ah1, ah2, ah3, bv.z, bv.w);   // hi*lo
                MMA_BF16(oacc[n], al0, al1, al2, al3, bv.x, bv.y);   // lo*hi
            }
        }
    }

    #pragma unroll
    for (int n = 0; n < 8; n++) {
        const int dcol = n*8 + 2*tig;
        *reinterpret_cast<float2*>(outbase + (size_t)r0*DD + dcol) =
            make_float2(oacc[n][0], oacc[n][1]);
        *reinterpret_cast<float2*>(outbase + (size_t)r1*DD + dcol) =
            make_float2(oacc[n][2], oacc[n][3]);
    }
}

extern "C" void kernel_launch(void* const* d_in, const int* in_sizes, int n_in,
                              void* d_out, int out_size) {
    const float* q    = (const float*)d_in[0];
    const float* k    = (const float*)d_in[1];
    const float* v    = (const float*)d_in[2];
    const int*   mask = (const int*)d_in[3];

    float* out = (float*)d_out;
    const size_t n_out  = (size_t)NB*NH*SS*DD;
    const size_t n_attn = (size_t)NB*NH*SS*SS;
    float* prob = out + n_out;
    float* attn = prob + n_attn;

    dim3 pgrid(64, NH, NB);
    pack_k_kernel<<<pgrid, 256>>>(k);
    pack_v_kernel<<<pgrid, 256>>>(v);
    pack_mask_kernel<<<(NB*SS*64*32)/256, 256>>>(mask);

    const int smem1 = K1_FLOATS * (int)sizeof(float);   // 17,408 B
    const int smem2 = K2_FLOATS * (int)sizeof(float);   // 16,384 B
    cudaFuncSetAttribute(sdpa_pass1_kernel,
                         cudaFuncAttributeMaxDynamicSharedMemorySize, smem1);
    cudaFuncSetAttribute(sdpa_pass1_kernel,
                         cudaFuncAttributePreferredSharedMemoryCarveout, 100);
    cudaFuncSetAttribute(sdpa_pass2_kernel,
                         cudaFuncAttributeMaxDynamicSharedMemorySize, smem2);
    cudaFuncSetAttribute(sdpa_pass2_kernel,
                         cudaFuncAttributePreferredSharedMemoryCarveout, 100);

    dim3 grid(SS/128, NH, NB);
    sdpa_pass1_kernel<<<grid, 256, smem1>>>(q, attn);
    sdpa_pass2_kernel<<<grid, 256, smem2>>>(out, prob, attn);
}

// round 12
// speedup vs baseline: 1.0992x; 1.0992x over previous
#include <cuda_runtime.h>
#include <cstdint>

#define SS 2048
#define DD 64
#define NH 16
#define NB 2
#define NEGV -1000000000.0f

// ---- pass1 smem (floats) ----
#define K1_DB  0                   // K db: 2 x 2048 floats (8KB tiles)
#define K1_MB  4096                // mask db: 2 x 128 words
#define K1_FLOATS 4352             // 17,408 B

// ---- pass2 smem (floats) ----
#define K2_PS 0                    // packed Ps: 128 x 32 = 4096 floats
#define K2_DB 4096                 // V db: 2 x 2048 floats
#define K2_LI (K2_DB + 4096)       // li[128]
#define K2_FLOATS (K2_LI + 128)    // 8320 floats = 33,280 B

// packed scratch: 64 tiles of 2048 floats per bh
__device__ float    g_kpk[(size_t)NB*NH*64*2048];
__device__ float    g_vpk[(size_t)NB*NH*64*2048];
__device__ unsigned g_mbits[(size_t)NB*SS*64];
__device__ float    g_li[(size_t)NB*NH*SS];

#define MMA_BF16(d, a0,a1,a2,a3, b0,b1) \
    asm volatile("mma.sync.aligned.m16n8k16.row.col.f32.bf16.bf16.f32 " \
        "{%0,%1,%2,%3}, {%4,%5,%6,%7}, {%8,%9}, {%0,%1,%2,%3};" \
        : "+f"((d)[0]), "+f"((d)[1]), "+f"((d)[2]), "+f"((d)[3]) \
        : "r"(a0), "r"(a1), "r"(a2), "r"(a3), "r"(b0), "r"(b1))

__device__ __forceinline__ uint32_t bf16pair(float x0, float x1) {
    uint32_t r;
    asm("cvt.rn.bf16x2.f32 %0, %1, %2;" : "=r"(r) : "f"(x1), "f"(x0));
    return r;
}
__device__ __forceinline__ void split_pair(float x0, float x1, uint32_t& hi, uint32_t& lo) {
    hi = bf16pair(x0, x1);
    float h0 = __uint_as_float(hi << 16);
    float h1 = __uint_as_float(hi & 0xffff0000u);
    lo = bf16pair(x0 - h0, x1 - h1);
}
__device__ __forceinline__ uint32_t smem_u32(const void* p) {
    uint32_t a;
    asm("{ .reg .u64 t; cvta.to.shared.u64 t, %1; cvt.u32.u64 %0, t; }" : "=r"(a) : "l"(p));
    return a;
}
// K slot (order {h0,h1,l0,l1}): 64 floats/row, kk 0..3
__device__ __forceinline__ int pk_k(int row, int kk, int tg) {
    return row*64 + ((((kk ^ (row & 3)) << 2) | tg) << 2);
}
// V slot (order {h0,h1,l0,l1}): 32 floats/row, kk 0..1
__device__ __forceinline__ int pk_v(int d, int kk, int tg) {
    return d*32 + ((((kk ^ (d & 1)) << 2) | tg) << 2);
}
// P slot (order {h0,l0,h1,l1}): 32 floats/row, kk 0..1
__device__ __forceinline__ int pk_p(int row, int kk, int tg) {
    return row*32 + ((((kk ^ (row & 1)) << 2) | tg) << 2);
}
__device__ __forceinline__ void cp16(uint32_t dst, const void* src) {
    asm volatile("cp.async.cg.shared.global [%0], [%1], 16;" :: "r"(dst), "l"(src));
}
__device__ __forceinline__ void cp4(uint32_t dst, const void* src) {
    asm volatile("cp.async.ca.shared.global [%0], [%1], 4;" :: "r"(dst), "l"(src));
}
__device__ __forceinline__ void cp_commit() { asm volatile("cp.async.commit_group;"); }
__device__ __forceinline__ void cp_wait0()  { asm volatile("cp.async.wait_group 0;" ::: "memory"); }

__device__ __forceinline__ void cp_tile8(uint32_t dst_byte, const float* src, int tid) {
    cp16(dst_byte + tid*16, src + tid*4);
    cp16(dst_byte + (tid+256)*16, src + (tid+256)*4);
}

// ---------------- prologue kernels ----------------
__global__ void pack_k_kernel(const float* __restrict__ kg) {
    const int kt = blockIdx.x, h = blockIdx.y, b = blockIdx.z;
    const int bh = b*NH + h;
    const float* base = kg + ((size_t)bh*SS + kt*32) * DD;
    float* out = g_kpk + ((size_t)bh*64 + kt) * 2048;
    for (int s = threadIdx.x; s < 512; s += 256) {
        int r = s >> 4, kk = (s >> 2) & 3, tg = s & 3;
        int c0 = kk*16 + tg*2;
        const float* kp = base + (size_t)r*DD;
        uint32_t bh0, bl0, bh1, bl1;
        split_pair(kp[c0],   kp[c0+1], bh0, bl0);
        split_pair(kp[c0+8], kp[c0+9], bh1, bl1);
        *reinterpret_cast<uint4*>(out + pk_k(r, kk, tg)) = make_uint4(bh0, bh1, bl0, bl1);
    }
}

__global__ void pack_v_kernel(const float* __restrict__ vg) {
    __shared__ float Vs[32*65];
    const int kt = blockIdx.x, h = blockIdx.y, b = blockIdx.z;
    const int bh = b*NH + h;
    const float* base = vg + ((size_t)bh*SS + kt*32) * DD;
    float* out = g_vpk + ((size_t)bh*64 + kt) * 2048;
    for (int i = threadIdx.x; i < 32*16; i += 256) {
        int k = i >> 4, d4 = (i & 15) << 2;
        float4 v = *reinterpret_cast<const float4*>(base + (size_t)k*DD + d4);
        Vs[k*65 + d4 + 0] = v.x; Vs[k*65 + d4 + 1] = v.y;
        Vs[k*65 + d4 + 2] = v.z; Vs[k*65 + d4 + 3] = v.w;
    }
    __syncthreads();
    for (int s = threadIdx.x; s < 512; s += 256) {
        int d = s >> 3, kk = (s >> 2) & 1, tg = s & 3;
        int c0 = kk*16 + tg*2;
        uint32_t bh0, bl0, bh1, bl1;
        split_pair(Vs[c0*65 + d],     Vs[(c0+1)*65 + d], bh0, bl0);
        split_pair(Vs[(c0+8)*65 + d], Vs[(c0+9)*65 + d], bh1, bl1);
        *reinterpret_cast<uint4*>(out + pk_v(d, kk, tg)) = make_uint4(bh0, bh1, bl0, bl1);
    }
}

__global__ void pack_mask_kernel(const int* __restrict__ maskg) {
    int gt = blockIdx.x*256 + threadIdx.x;
    int widx = gt >> 5;
    int lane = gt & 31;
    int w = widx & 63;
    int row = (widx >> 6) & (SS - 1);
    int b = widx >> 17;
    int c = w*32 + lane;
    unsigned nz = maskg[((size_t)b*SS + row)*SS + c] != 0;
    unsigned bits = __ballot_sync(0xffffffffu, nz);
    if (lane == 0) g_mbits[widx] = bits;
}

// ---------------- pass 1: scores + attn + 1/l ----------------
__global__ __launch_bounds__(256, 3)
void sdpa_pass1_kernel(const float* __restrict__ qg, float* __restrict__ attng)
{
    extern __shared__ float sm[];
    unsigned* maskbuf = reinterpret_cast<unsigned*>(sm + K1_MB);
    const uint32_t db_byte = smem_u32(sm + K1_DB);
    const uint32_t mb_byte = smem_u32(sm + K1_MB);

    const int tid = threadIdx.x;
    const int wid = tid >> 5;
    const int lid = tid & 31;
    const int grp = lid >> 2;
    const int tig = lid & 3;
    const int mrow0 = wid * 16;
    const int g3 = grp & 3;

    const int q0 = blockIdx.x * 128;
    const int h  = blockIdx.y;
    const int b  = blockIdx.z;
    const int bh = b*NH + h;

    const float* qbase = qg + ((size_t)bh*SS + q0) * DD;
    float* attnbase = attng + ((size_t)bh*SS + q0) * SS;
    const float* kpk = g_kpk + (size_t)bh*64*2048;
    const unsigned* mbits = g_mbits + ((size_t)b*SS + q0)*64;

    // prefetch K tile 0 + mask col 0
    cp_tile8(db_byte, kpk, tid);
    if (tid < 128) cp4(mb_byte + tid*4, mbits + (size_t)tid*64);
    cp_commit();

    // ---- Q fragments resident in registers (pre-scaled by 0.125, exact) ----
    const int r0 = mrow0 + grp, r1 = r0 + 8;
    uint32_t qh[4][4], ql[4][4];
    #pragma unroll
    for (int kk = 0; kk < 4; kk++) {
        const int c0 = kk*16 + 2*tig;
        float2 x00 = *reinterpret_cast<const float2*>(qbase + (size_t)r0*DD + c0);
        float2 x10 = *reinterpret_cast<const float2*>(qbase + (size_t)r1*DD + c0);
        float2 x01 = *reinterpret_cast<const float2*>(qbase + (size_t)r0*DD + c0 + 8);
        float2 x11 = *reinterpret_cast<const float2*>(qbase + (size_t)r1*DD + c0 + 8);
        split_pair(x00.x*0.125f, x00.y*0.125f, qh[kk][0], ql[kk][0]);
        split_pair(x10.x*0.125f, x10.y*0.125f, qh[kk][1], ql[kk][1]);
        split_pair(x01.x*0.125f, x01.y*0.125f, qh[kk][2], ql[kk][2]);
        split_pair(x11.x*0.125f, x11.y*0.125f, qh[kk][3], ql[kk][3]);
    }

    float lrun[2] = {0.0f, 0.0f};

    for (int t = 0; t < 64; t++) {
        cp_wait0();
        __syncthreads();
        if (t < 63) {
            cp_tile8(db_byte + ((t+1)&1)*8192, kpk + (size_t)(t+1)*2048, tid);
            if (tid < 128)
                cp4(mb_byte + ((t+1)&1)*512 + tid*4, mbits + (size_t)tid*64 + (t+1));
            cp_commit();
        }

        const float* kbuf = sm + K1_DB + (t&1)*2048;
        const float* bbase = kbuf + grp*64 + tig*4;

        float acc[4][4];
        #pragma unroll
        for (int n = 0; n < 4; n++) {
            acc[n][0] = 0.f; acc[n][1] = 0.f; acc[n][2] = 0.f; acc[n][3] = 0.f;
        }

        #pragma unroll
        for (int kk = 0; kk < 4; kk++) {
            const float* bk = bbase + ((kk ^ g3) << 4);
            #pragma unroll
            for (int n = 0; n < 4; n++) {
                uint4 bv = *reinterpret_cast<const uint4*>(bk + n*512);
                MMA_BF16(acc[n], qh[kk][0], qh[kk][1], qh[kk][2], qh[kk][3], bv.x, bv.y);
                MMA_BF16(acc[n], qh[kk][0], qh[kk][1], qh[kk][2], qh[kk][3], bv.z, bv.w);
                MMA_BF16(acc[n], ql[kk][0], ql[kk][1], ql[kk][2], ql[kk][3], bv.x, bv.y);
            }
        }

        // epilogue: mask + attn STG + running row-sums (no max subtraction)
        const unsigned word0 = maskbuf[(t&1)*128 + r0];
        const unsigned word1 = maskbuf[(t&1)*128 + r1];
        float ls0 = 0.0f, ls1 = 0.0f;
        #pragma unroll
        for (int n = 0; n < 4; n++) {
            const int c = n*8 + 2*tig;
            float s0 = acc[n][0] + (((word0 >> c) & 1u) ? 0.0f : NEGV);
            float s1 = acc[n][1] + (((word0 >> (c+1)) & 1u) ? 0.0f : NEGV);
            float s2 = acc[n][2] + (((word1 >> c) & 1u) ? 0.0f : NEGV);
            float s3 = acc[n][3] + (((word1 >> (c+1)) & 1u) ? 0.0f : NEGV);
            const int kcol = t*32 + c;
            *reinterpret_cast<float2*>(attnbase + (size_t)r0*SS + kcol) = make_float2(s0, s1);
            *reinterpret_cast<float2*>(attnbase + (size_t)r1*SS + kcol) = make_float2(s2, s3);
            ls0 += __expf(s0) + __expf(s1);
            ls1 += __expf(s2) + __expf(s3);
        }
        lrun[0] += ls0;
        lrun[1] += ls1;
    }

    // combine row-sums across the 4 tig lanes
    #pragma unroll
    for (int hh = 0; hh < 2; hh++) {
        float l = lrun[hh];
        l += __shfl_xor_sync(0xffffffffu, l, 1);
        l += __shfl_xor_sync(0xffffffffu, l, 2);
        lrun[hh] = l;
    }
    if (tig == 0) {
        float* lib = g_li + (size_t)bh*SS + q0;
        lib[r0] = 1.0f / lrun[0];
        lib[r1] = 1.0f / lrun[1];
    }
}

// ---------------- pass 2: prob + O ----------------
__global__ __launch_bounds__(256, 4)
void sdpa_pass2_kernel(float* __restrict__ outg, float* __restrict__ probg,
                       const float* __restrict__ attng)
{
    extern __shared__ float sm[];
    float* Ps = sm + K2_PS;   // packed P
    float* sm_li = sm + K2_LI;
    const uint32_t db_byte = smem_u32(sm + K2_DB);

    const int tid = threadIdx.x;
    const int wid = tid >> 5;
    const int lid = tid & 31;
    const int grp = lid >> 2;
    const int tig = lid & 3;
    const int mrow0 = wid * 16;

    const int q0 = blockIdx.x * 128;
    const int h  = blockIdx.y;
    const int b  = blockIdx.z;
    const int bh = b*NH + h;

    const float* attnbase = attng + ((size_t)bh*SS + q0) * SS;
    float* probbase = probg + ((size_t)bh*SS + q0) * SS;
    float* outbase  = outg  + ((size_t)bh*SS + q0) * DD;
    const float* vpk = g_vpk + (size_t)bh*64*2048;

    if (tid < 128) sm_li[tid] = g_li[(size_t)bh*SS + q0 + tid];

    cp_tile8(db_byte, vpk, tid);
    cp_commit();

    float oacc[8][4];
    #pragma unroll
    for (int n = 0; n < 8; n++) {
        oacc[n][0] = 0.f; oacc[n][1] = 0.f; oacc[n][2] = 0.f; oacc[n][3] = 0.f;
    }

    const int prow_base = (mrow0 + grp)*32;
    const int prow_sw   = ((mrow0 + grp) & 1);

    for (int t = 0; t < 64; t++) {
        cp_wait0();
        __syncthreads();   // V buf t visible; compute(t-1) done; li visible (t=0)
        if (t < 63) {
            cp_tile8(db_byte + ((t+1)&1)*8192, vpk + (size_t)(t+1)*2048, tid);
            cp_commit();
        }

        // warp-private staging: coalesced attn LDG + prob STG + packed-P STS
        #pragma unroll
        for (int j = 0; j < 4; j++) {
            int idx = j*32 + lid;
            int row = mrow0 + (idx >> 3);
            int c4  = (idx & 7) << 2;
            size_t gi = (size_t)row*SS + t*32 + c4;
            float4 sv = *reinterpret_cast<const float4*>(attnbase + gi);
            float li = sm_li[row];
            float4 pv;
            pv.x = __expf(sv.x) * li;
            pv.y = __expf(sv.y) * li;
            pv.z = __expf(sv.z) * li;
            pv.w = __expf(sv.w) * li;
            *reinterpret_cast<float4*>(probbase + gi) = pv;
            uint32_t h0, l0, h1, l1;
            split_pair(pv.x, pv.y, h0, l0);
            split_pair(pv.z, pv.w, h1, l1);
            int kk = c4 >> 4;
            int r  = c4 & 15;
            int half = r >> 3;           // 0 or 1
            int tg = (r & 7) >> 1;       // 0 or 2
            uint32_t* sp = reinterpret_cast<uint32_t*>(Ps + pk_p(row, kk, tg) + half*2);
            *reinterpret_cast<uint2*>(sp)     = make_uint2(h0, l0);
            *reinterpret_cast<uint2*>(sp + 4) = make_uint2(h1, l1);   // tg+1 slot
        }
        __syncwarp();

        const float* vbuf = sm + K2_DB + (t&1)*2048;
        #pragma unroll
        for (int kk = 0; kk < 2; kk++) {
            uint4 pa = *reinterpret_cast<const uint4*>(
                Ps + prow_base + ((((kk ^ prow_sw) << 2) | tig) << 2));
            uint4 pb = *reinterpret_cast<const uint4*>(
                Ps + prow_base + 256 + ((((kk ^ prow_sw) << 2) | tig) << 2));
            const float* vb = vbuf + grp*32 + tig*4 + (((kk ^ (grp & 1)) << 4));
            #pragma unroll
            for (int n = 0; n < 8; n++) {
                uint4 bv = *reinterpret_cast<const uint4*>(vb + n*256);
                MMA_BF16(oacc[n], pa.x, pb.x, pa.z, pb.z, bv.x, bv.y);   // hi*hi
                MMA_BF16(oacc[n], pa.x, pb.x, pa.z, pb.z, bv.z, bv.w);   // hi*lo
                MMA_BF16(oacc[n], pa.y, pb.y, pa.w, pb.w, bv.x, bv.y);   // lo*hi
            }
        }
    }

    #pragma unroll
    for (int n = 0; n < 8; n++) {
        const int dcol = n*8 + 2*tig;
        *reinterpret_cast<float2*>(outbase + (size_t)(mrow0 + grp)*DD + dcol) =
            make_float2(oacc[n][0], oacc[n][1]);
        *reinterpret_cast<float2*>(outbase + (size_t)(mrow0 + grp + 8)*DD + dcol) =
            make_float2(oacc[n][2], oacc[n][3]);
    }
}

extern "C" void kernel_launch(void* const* d_in, const int* in_sizes, int n_in,
                              void* d_out, int out_size) {
    const float* q    = (const float*)d_in[0];
    const float* k    = (const float*)d_in[1];
    const float* v    = (const float*)d_in[2];
    const int*   mask = (const int*)d_in[3];

    float* out = (float*)d_out;
    const size_t n_out  = (size_t)NB*NH*SS*DD;
    const size_t n_attn = (size_t)NB*NH*SS*SS;
    float* prob = out + n_out;
    float* attn = prob + n_attn;

    dim3 pgrid(64, NH, NB);
    pack_k_kernel<<<pgrid, 256>>>(k);
    pack_v_kernel<<<pgrid, 256>>>(v);
    pack_mask_kernel<<<(NB*SS*64*32)/256, 256>>>(mask);

    const int smem1 = K1_FLOATS * (int)sizeof(float);   // 17,408 B
    const int smem2 = K2_FLOATS * (int)sizeof(float);   // 33,280 B
    cudaFuncSetAttribute(sdpa_pass1_kernel,
                         cudaFuncAttributeMaxDynamicSharedMemorySize, smem1);
    cudaFuncSetAttribute(sdpa_pass1_kernel,
                         cudaFuncAttributePreferredSharedMemoryCarveout, 100);
    cudaFuncSetAttribute(sdpa_pass2_kernel,
                         cudaFuncAttributeMaxDynamicSharedMemorySize, smem2);
    cudaFuncSetAttribute(sdpa_pass2_kernel,
                         cudaFuncAttributePreferredSharedMemoryCarveout, 100);

    dim3 grid(SS/128, NH, NB);
    sdpa_pass1_kernel<<<grid, 256, smem1>>>(q, attn);
    sdpa_pass2_kernel<<<grid, 256, smem2>>>(out, prob, attn);
}

// round 13
// speedup vs baseline: 1.1223x; 1.0211x over previous
#include <cuda_runtime.h>
#include <cstdint>

#define SS 2048
#define DD 64
#define NH 16
#define NB 2
#define NEGV -1000000000.0f

// ---- fused kernel smem (floats) ----
// per buf: K tile 2048 fl @0, V tile 2048 fl @2048 ; two bufs
#define A_DB  0
#define A_MB  8192                  // mask db: 2 x 128 words
#define A_FLOATS 8448               // 33,792 B

// packed scratch: 64 tiles of 2048 floats per bh
__device__ float    g_kpk[(size_t)NB*NH*64*2048];
__device__ float    g_vpk[(size_t)NB*NH*64*2048];
__device__ unsigned g_mbits[(size_t)NB*SS*64];
__device__ float    g_li[(size_t)NB*NH*SS];

#define MMA_BF16(d, a0,a1,a2,a3, b0,b1) \
    asm volatile("mma.sync.aligned.m16n8k16.row.col.f32.bf16.bf16.f32 " \
        "{%0,%1,%2,%3}, {%4,%5,%6,%7}, {%8,%9}, {%0,%1,%2,%3};" \
        : "+f"((d)[0]), "+f"((d)[1]), "+f"((d)[2]), "+f"((d)[3]) \
        : "r"(a0), "r"(a1), "r"(a2), "r"(a3), "r"(b0), "r"(b1))

__device__ __forceinline__ uint32_t bf16pair(float x0, float x1) {
    uint32_t r;
    asm("cvt.rn.bf16x2.f32 %0, %1, %2;" : "=r"(r) : "f"(x1), "f"(x0));
    return r;
}
__device__ __forceinline__ void split_pair(float x0, float x1, uint32_t& hi, uint32_t& lo) {
    hi = bf16pair(x0, x1);
    float h0 = __uint_as_float(hi << 16);
    float h1 = __uint_as_float(hi & 0xffff0000u);
    lo = bf16pair(x0 - h0, x1 - h1);
}
__device__ __forceinline__ uint32_t smem_u32(const void* p) {
    uint32_t a;
    asm("{ .reg .u64 t; cvta.to.shared.u64 t, %1; cvt.u32.u64 %0, t; }" : "=r"(a) : "l"(p));
    return a;
}
// K slot (order {h0,h1,l0,l1}): 64 floats/row, kk 0..3
__device__ __forceinline__ int pk_k(int row, int kk, int tg) {
    return row*64 + ((((kk ^ (row & 3)) << 2) | tg) << 2);
}
// V slot (order {h0,h1,l0,l1}): 32 floats/row, kk 0..1
__device__ __forceinline__ int pk_v(int d, int kk, int tg) {
    return d*32 + ((((kk ^ (d & 1)) << 2) | tg) << 2);
}
__device__ __forceinline__ void cp16(uint32_t dst, const void* src) {
    asm volatile("cp.async.cg.shared.global [%0], [%1], 16;" :: "r"(dst), "l"(src));
}
__device__ __forceinline__ void cp4(uint32_t dst, const void* src) {
    asm volatile("cp.async.ca.shared.global [%0], [%1], 4;" :: "r"(dst), "l"(src));
}
__device__ __forceinline__ void cp_commit() { asm volatile("cp.async.commit_group;"); }
__device__ __forceinline__ void cp_wait0()  { asm volatile("cp.async.wait_group 0;" ::: "memory"); }

// ---------------- prologue kernels ----------------
__global__ void pack_k_kernel(const float* __restrict__ kg) {
    const int kt = blockIdx.x, h = blockIdx.y, b = blockIdx.z;
    const int bh = b*NH + h;
    const float* base = kg + ((size_t)bh*SS + kt*32) * DD;
    float* out = g_kpk + ((size_t)bh*64 + kt) * 2048;
    for (int s = threadIdx.x; s < 512; s += 256) {
        int r = s >> 4, kk = (s >> 2) & 3, tg = s & 3;
        int c0 = kk*16 + tg*2;
        const float* kp = base + (size_t)r*DD;
        uint32_t bh0, bl0, bh1, bl1;
        split_pair(kp[c0],   kp[c0+1], bh0, bl0);
        split_pair(kp[c0+8], kp[c0+9], bh1, bl1);
        *reinterpret_cast<uint4*>(out + pk_k(r, kk, tg)) = make_uint4(bh0, bh1, bl0, bl1);
    }
}

__global__ void pack_v_kernel(const float* __restrict__ vg) {
    __shared__ float Vs[32*65];
    const int kt = blockIdx.x, h = blockIdx.y, b = blockIdx.z;
    const int bh = b*NH + h;
    const float* base = vg + ((size_t)bh*SS + kt*32) * DD;
    float* out = g_vpk + ((size_t)bh*64 + kt) * 2048;
    for (int i = threadIdx.x; i < 32*16; i += 256) {
        int k = i >> 4, d4 = (i & 15) << 2;
        float4 v = *reinterpret_cast<const float4*>(base + (size_t)k*DD + d4);
        Vs[k*65 + d4 + 0] = v.x; Vs[k*65 + d4 + 1] = v.y;
        Vs[k*65 + d4 + 2] = v.z; Vs[k*65 + d4 + 3] = v.w;
    }
    __syncthreads();
    for (int s = threadIdx.x; s < 512; s += 256) {
        int d = s >> 3, kk = (s >> 2) & 1, tg = s & 3;
        int c0 = kk*16 + tg*2;
        uint32_t bh0, bl0, bh1, bl1;
        split_pair(Vs[c0*65 + d],     Vs[(c0+1)*65 + d], bh0, bl0);
        split_pair(Vs[(c0+8)*65 + d], Vs[(c0+9)*65 + d], bh1, bl1);
        *reinterpret_cast<uint4*>(out + pk_v(d, kk, tg)) = make_uint4(bh0, bh1, bl0, bl1);
    }
}

__global__ void pack_mask_kernel(const int* __restrict__ maskg) {
    int gt = blockIdx.x*256 + threadIdx.x;
    int widx = gt >> 5;
    int lane = gt & 31;
    int w = widx & 63;
    int row = (widx >> 6) & (SS - 1);
    int b = widx >> 17;
    int c = w*32 + lane;
    unsigned nz = maskg[((size_t)b*SS + row)*SS + c] != 0;
    unsigned bits = __ballot_sync(0xffffffffu, nz);
    if (lane == 0) g_mbits[widx] = bits;
}

// ---------------- fused: scores + attn + l + O ----------------
__global__ __launch_bounds__(256, 2)
void sdpa_fused_kernel(const float* __restrict__ qg, float* __restrict__ attng,
                       float* __restrict__ outg)
{
    extern __shared__ float sm[];
    unsigned* maskbuf = reinterpret_cast<unsigned*>(sm + A_MB);
    const uint32_t db_byte = smem_u32(sm + A_DB);
    const uint32_t mb_byte = smem_u32(sm + A_MB);

    const int tid = threadIdx.x;
    const int wid = tid >> 5;
    const int lid = tid & 31;
    const int grp = lid >> 2;
    const int tig = lid & 3;
    const int mrow0 = wid * 16;
    const int g3 = grp & 3;
    const int g1 = grp & 1;

    const int q0 = blockIdx.x * 128;
    const int h  = blockIdx.y;
    const int b  = blockIdx.z;
    const int bh = b*NH + h;

    const float* qbase = qg + ((size_t)bh*SS + q0) * DD;
    float* attnbase = attng + ((size_t)bh*SS + q0) * SS;
    float* outbase  = outg  + ((size_t)bh*SS + q0) * DD;
    const float* kpk = g_kpk + (size_t)bh*64*2048;
    const float* vpk = g_vpk + (size_t)bh*64*2048;
    const unsigned* mbits = g_mbits + ((size_t)b*SS + q0)*64;

    // prefetch K+V tile 0 + mask col 0
    cp16(db_byte + tid*16,          kpk + tid*4);
    cp16(db_byte + (tid+256)*16,    kpk + (tid+256)*4);
    cp16(db_byte + 8192 + tid*16,       vpk + tid*4);
    cp16(db_byte + 8192 + (tid+256)*16, vpk + (tid+256)*4);
    if (tid < 128) cp4(mb_byte + tid*4, mbits + (size_t)tid*64);
    cp_commit();

    // ---- Q fragments resident in registers (pre-scaled by 0.125, exact) ----
    const int r0 = mrow0 + grp, r1 = r0 + 8;
    uint32_t qh[4][4], ql[4][4];
    #pragma unroll
    for (int kk = 0; kk < 4; kk++) {
        const int c0 = kk*16 + 2*tig;
        float2 x00 = *reinterpret_cast<const float2*>(qbase + (size_t)r0*DD + c0);
        float2 x10 = *reinterpret_cast<const float2*>(qbase + (size_t)r1*DD + c0);
        float2 x01 = *reinterpret_cast<const float2*>(qbase + (size_t)r0*DD + c0 + 8);
        float2 x11 = *reinterpret_cast<const float2*>(qbase + (size_t)r1*DD + c0 + 8);
        split_pair(x00.x*0.125f, x00.y*0.125f, qh[kk][0], ql[kk][0]);
        split_pair(x10.x*0.125f, x10.y*0.125f, qh[kk][1], ql[kk][1]);
        split_pair(x01.x*0.125f, x01.y*0.125f, qh[kk][2], ql[kk][2]);
        split_pair(x11.x*0.125f, x11.y*0.125f, qh[kk][3], ql[kk][3]);
    }

    float lrun[2] = {0.0f, 0.0f};
    float oacc[8][4];
    #pragma unroll
    for (int n = 0; n < 8; n++) {
        oacc[n][0] = 0.f; oacc[n][1] = 0.f; oacc[n][2] = 0.f; oacc[n][3] = 0.f;
    }

    for (int t = 0; t < 64; t++) {
        cp_wait0();
        __syncthreads();
        if (t < 63) {
            const uint32_t nb = db_byte + ((t+1)&1)*16384;
            const float* kp = kpk + (size_t)(t+1)*2048;
            const float* vp = vpk + (size_t)(t+1)*2048;
            cp16(nb + tid*16,              kp + tid*4);
            cp16(nb + (tid+256)*16,        kp + (tid+256)*4);
            cp16(nb + 8192 + tid*16,       vp + tid*4);
            cp16(nb + 8192 + (tid+256)*16, vp + (tid+256)*4);
            if (tid < 128)
                cp4(mb_byte + ((t+1)&1)*512 + tid*4, mbits + (size_t)tid*64 + (t+1));
            cp_commit();
        }

        const float* kbuf = sm + A_DB + (t&1)*4096;
        const float* vbuf = kbuf + 2048;
        const float* bbase = kbuf + grp*64 + tig*4;

        float acc[4][4];
        #pragma unroll
        for (int n = 0; n < 4; n++) {
            acc[n][0] = 0.f; acc[n][1] = 0.f; acc[n][2] = 0.f; acc[n][3] = 0.f;
        }

        // ---- QK^T ----
        #pragma unroll
        for (int kk = 0; kk < 4; kk++) {
            const float* bk = bbase + ((kk ^ g3) << 4);
            #pragma unroll
            for (int n = 0; n < 4; n++) {
                uint4 bv = *reinterpret_cast<const uint4*>(bk + n*512);
                MMA_BF16(acc[n], qh[kk][0], qh[kk][1], qh[kk][2], qh[kk][3], bv.x, bv.y);
                MMA_BF16(acc[n], qh[kk][0], qh[kk][1], qh[kk][2], qh[kk][3], bv.z, bv.w);
                MMA_BF16(acc[n], ql[kk][0], ql[kk][1], ql[kk][2], ql[kk][3], bv.x, bv.y);
            }
        }

        // ---- epilogue: mask + attn STG + e = exp(s) + row sums ----
        const unsigned word0 = maskbuf[(t&1)*128 + r0];
        const unsigned word1 = maskbuf[(t&1)*128 + r1];
        float ls0 = 0.0f, ls1 = 0.0f;
        #pragma unroll
        for (int n = 0; n < 4; n++) {
            const int c = n*8 + 2*tig;
            float s0 = acc[n][0] + (((word0 >> c) & 1u) ? 0.0f : NEGV);
            float s1 = acc[n][1] + (((word0 >> (c+1)) & 1u) ? 0.0f : NEGV);
            float s2 = acc[n][2] + (((word1 >> c) & 1u) ? 0.0f : NEGV);
            float s3 = acc[n][3] + (((word1 >> (c+1)) & 1u) ? 0.0f : NEGV);
            const int kcol = t*32 + c;
            *reinterpret_cast<float2*>(attnbase + (size_t)r0*SS + kcol) = make_float2(s0, s1);
            *reinterpret_cast<float2*>(attnbase + (size_t)r1*SS + kcol) = make_float2(s2, s3);
            float e0 = __expf(s0), e1 = __expf(s1), e2 = __expf(s2), e3 = __expf(s3);
            acc[n][0] = e0; acc[n][1] = e1; acc[n][2] = e2; acc[n][3] = e3;
            ls0 += e0 + e1;
            ls1 += e2 + e3;
        }
        lrun[0] += ls0;
        lrun[1] += ls1;

        // ---- PV: e-fragments (already in A-layout) x V tile ----
        #pragma unroll
        for (int kk = 0; kk < 2; kk++) {
            uint32_t ah0, al0, ah1, al1, ah2, al2, ah3, al3;
            split_pair(acc[2*kk][0],   acc[2*kk][1],   ah0, al0);   // r0, k-lo
            split_pair(acc[2*kk][2],   acc[2*kk][3],   ah1, al1);   // r1, k-lo
            split_pair(acc[2*kk+1][0], acc[2*kk+1][1], ah2, al2);   // r0, k-hi
            split_pair(acc[2*kk+1][2], acc[2*kk+1][3], ah3, al3);   // r1, k-hi
            const float* vb = vbuf + grp*32 + tig*4 + ((kk ^ g1) << 4);
            #pragma unroll
            for (int n = 0; n < 8; n++) {
                uint4 bv = *reinterpret_cast<const uint4*>(vb + n*256);
                MMA_BF16(oacc[n], ah0, ah1, ah2, ah3, bv.x, bv.y);   // hi*hi
                MMA_BF16(oacc[n], ah0, ah1, ah2, ah3, bv.z, bv.w);   // hi*lo
                MMA_BF16(oacc[n], al0, al1, al2, al3, bv.x, bv.y);   // lo*hi
            }
        }
    }

    // ---- combine row-sums across the 4 tig lanes (all lanes get result) ----
    #pragma unroll
    for (int hh = 0; hh < 2; hh++) {
        float l = lrun[hh];
        l += __shfl_xor_sync(0xffffffffu, l, 1);
        l += __shfl_xor_sync(0xffffffffu, l, 2);
        lrun[hh] = l;
    }
    const float li0 = 1.0f / lrun[0];
    const float li1 = 1.0f / lrun[1];
    if (tig == 0) {
        float* lib = g_li + (size_t)bh*SS + q0;
        lib[r0] = li0;
        lib[r1] = li1;
    }

    // ---- O = O_unnorm * (1/l) ----
    #pragma unroll
    for (int n = 0; n < 8; n++) {
        const int dcol = n*8 + 2*tig;
        *reinterpret_cast<float2*>(outbase + (size_t)r0*DD + dcol) =
            make_float2(oacc[n][0]*li0, oacc[n][1]*li0);
        *reinterpret_cast<float2*>(outbase + (size_t)r1*DD + dcol) =
            make_float2(oacc[n][2]*li1, oacc[n][3]*li1);
    }
}

// ---------------- prob: streaming exp * (1/l) ----------------
__global__ __launch_bounds__(256)
void prob_kernel(float* __restrict__ probg, const float* __restrict__ attng)
{
    const int row = blockIdx.x;             // 0 .. NB*NH*SS-1
    const float li = g_li[row];
    const float4* a = reinterpret_cast<const float4*>(attng + (size_t)row*SS);
    float4* p = reinterpret_cast<float4*>(probg + (size_t)row*SS);
    #pragma unroll
    for (int j = 0; j < 2; j++) {
        int i = j*256 + threadIdx.x;
        float4 s = a[i];
        float4 pv;
        pv.x = __expf(s.x) * li;
        pv.y = __expf(s.y) * li;
        pv.z = __expf(s.z) * li;
        pv.w = __expf(s.w) * li;
        p[i] = pv;
    }
}

extern "C" void kernel_launch(void* const* d_in, const int* in_sizes, int n_in,
                              void* d_out, int out_size) {
    const float* q    = (const float*)d_in[0];
    const float* k    = (const float*)d_in[1];
    const float* v    = (const float*)d_in[2];
    const int*   mask = (const int*)d_in[3];

    float* out = (float*)d_out;
    const size_t n_out  = (size_t)NB*NH*SS*DD;
    const size_t n_attn = (size_t)NB*NH*SS*SS;
    float* prob = out + n_out;
    float* attn = prob + n_attn;

    dim3 pgrid(64, NH, NB);
    pack_k_kernel<<<pgrid, 256>>>(k);
    pack_v_kernel<<<pgrid, 256>>>(v);
    pack_mask_kernel<<<(NB*SS*64*32)/256, 256>>>(mask);

    const int smemA = A_FLOATS * (int)sizeof(float);   // 33,792 B
    cudaFuncSetAttribute(sdpa_fused_kernel,
                         cudaFuncAttributeMaxDynamicSharedMemorySize, smemA);
    cudaFuncSetAttribute(sdpa_fused_kernel,
                         cudaFuncAttributePreferredSharedMemoryCarveout, 100);

    dim3 grid(SS/128, NH, NB);
    sdpa_fused_kernel<<<grid, 256, smemA>>>(q, attn, out);
    prob_kernel<<<NB*NH*SS, 256>>>(prob, attn);
}